// round 13
// baseline (speedup 1.0000x reference)
#include <cuda_runtime.h>
#include <cuda_fp16.h>

#define N_NODES_MAX 100000
#define NE_MAX 1600000
#define N_GRAPHS 256
#define HID 64
#define N_TASKS 10
#define EPG 32   // edges per 16-thread group chunk (dst-sorted)

// ---------------- scratch (no allocations allowed) ----------------
__device__ __align__(16) float d_agg[N_NODES_MAX * HID];
__device__ __align__(16) float d_hA[N_NODES_MAX * HID];
__device__ __align__(16) float d_hB[N_NODES_MAX * HID];
__device__ __align__(16) __half d_hh[N_NODES_MAX * HID];   // fp16 copy of current node features
__device__ __align__(16) float d_pooled[N_GRAPHS * HID];
__device__ __align__(16) float d_cnt[N_GRAPHS];
__device__ __align__(16) float d_W12[16 * 128];   // [We1 | We1@We2]
__device__ __align__(16) float d_b12[128];        // [be1 | be1@We2+be2]
// CSR / sorted-edge scratch
__device__ int d_hist[N_NODES_MAX];
__device__ int d_cur[N_NODES_MAX];
__device__ int d_offs[N_NODES_MAX + 1];
__device__ int d_bsum[128];
__device__ int d_eid[NE_MAX];
__device__ __align__(8) int2 d_sd[NE_MAX];        // packed (src, dst) in sorted order
// transformed edge features, dst-sorted order, bias included, fp16 (205 MB each)
__device__ __align__(16) __half d_ea1h[(long long)NE_MAX * HID];
__device__ __align__(16) __half d_ea2h[(long long)NE_MAX * HID];

// ---------------- prep ----------------
__global__ void prep_kernel(const float* __restrict__ We1, const float* __restrict__ be1,
                            const float* __restrict__ We2, const float* __restrict__ be2,
                            float* __restrict__ W12, float* __restrict__ b12) {
    int idx = blockIdx.x * blockDim.x + threadIdx.x;
    if (idx < 16 * 128) {
        int k = idx >> 7, j = idx & 127;
        if (j < 64) {
            W12[idx] = We1[k * HID + j];
        } else {
            int jj = j - 64;
            float acc = 0.f;
            #pragma unroll 8
            for (int m = 0; m < HID; m++) acc += We1[k * HID + m] * We2[m * HID + jj];
            W12[idx] = acc;
        }
    } else if (idx < 16 * 128 + 128) {
        int j = idx - 16 * 128;
        if (j < 64) {
            b12[j] = be1[j];
        } else {
            int jj = j - 64;
            float acc = be2[jj];
            #pragma unroll 8
            for (int m = 0; m < HID; m++) acc += be1[m] * We2[m * HID + jj];
            b12[j] = acc;
        }
    }
}

// ---------------- zero / convert ----------------
__global__ void zero2_i(int* __restrict__ p, int* __restrict__ q, int n) {
    int i = blockIdx.x * blockDim.x + threadIdx.x;
    if (i < n) { p[i] = 0; q[i] = 0; }
}
// fp32 -> fp16 convert (node features), 2 elems per thread
__global__ void cvt_h_kernel(const float* __restrict__ in, __half* __restrict__ outh, int n2) {
    int i = blockIdx.x * blockDim.x + threadIdx.x;
    if (i < n2) {
        float2 v = *reinterpret_cast<const float2*>(in + 2 * i);
        __half2 h = __floats2half2_rn(v.x, v.y);
        *reinterpret_cast<__half2*>(outh + 2 * i) = h;
    }
}

// ---------------- CSR build ----------------
__global__ void hist_kernel(const int* __restrict__ dst, int* __restrict__ hist, int nE) {
    int e = blockIdx.x * blockDim.x + threadIdx.x;
    if (e < nE) atomicAdd(&hist[__ldcs(dst + e)], 1);
}

__global__ void scan_block_kernel(const int* __restrict__ hist, int* __restrict__ offs,
                                  int* __restrict__ bsum, int nN) {
    __shared__ int s[1024];
    int i = blockIdx.x * 1024 + threadIdx.x;
    int v = (i < nN) ? hist[i] : 0;
    s[threadIdx.x] = v;
    __syncthreads();
    for (int off = 1; off < 1024; off <<= 1) {
        int add = (threadIdx.x >= off) ? s[threadIdx.x - off] : 0;
        __syncthreads();
        s[threadIdx.x] += add;
        __syncthreads();
    }
    if (i < nN) offs[i] = s[threadIdx.x] - v;
    if (threadIdx.x == 1023) bsum[blockIdx.x] = s[1023];
}
__global__ void scan_top_kernel(int* __restrict__ bsum, int nB) {
    __shared__ int s[128];
    int v = (threadIdx.x < nB) ? bsum[threadIdx.x] : 0;
    s[threadIdx.x] = v;
    __syncthreads();
    for (int off = 1; off < 128; off <<= 1) {
        int add = (threadIdx.x >= off) ? s[threadIdx.x - off] : 0;
        __syncthreads();
        s[threadIdx.x] += add;
        __syncthreads();
    }
    if (threadIdx.x < nB) bsum[threadIdx.x] = s[threadIdx.x] - v;
}
__global__ void scan_add_kernel(int* __restrict__ offs, const int* __restrict__ bsum,
                                int nN, int nE) {
    int i = blockIdx.x * 1024 + threadIdx.x;
    if (i < nN) offs[i] += bsum[blockIdx.x];
    if (i == 0) offs[nN] = nE;
}

__global__ void scatter_kernel(const int* __restrict__ src, const int* __restrict__ dst,
                               const int* __restrict__ offs, int* __restrict__ cur,
                               int* __restrict__ eid_s, int2* __restrict__ sd, int nE) {
    int e = blockIdx.x * blockDim.x + threadIdx.x;
    if (e < nE) {
        int d = __ldcs(dst + e);
        int s = __ldcs(src + e);
        int p = atomicAdd(&cur[d], 1);
        int i = offs[d] + p;
        eid_s[i] = e;
        sd[i] = make_int2(s, d);
    }
}

// ---------------- transform: ea1h / ea2h in sorted order, fp16; 4 edges per warp-iter ----------------
__global__ void __launch_bounds__(256) transform_kernel(
    const float* __restrict__ ea,      // [E,16] original order
    const int* __restrict__ eid_s,
    const float* __restrict__ W12,     // [16,128]
    const float* __restrict__ b12,     // [128]
    __half* __restrict__ ea1h,         // [E,64] sorted
    __half* __restrict__ ea2h,         // [E,64] sorted
    int nE)
{
    const int lane = threadIdx.x & 31;
    const int t16 = lane & 15;
    long long warp = blockIdx.x * (blockDim.x >> 5) + (threadIdx.x >> 5);
    const long long stride = (long long)gridDim.x * (blockDim.x >> 5) * 4;

    float4 w[16];
    #pragma unroll
    for (int k = 0; k < 16; k++) w[k] = *(const float4*)(W12 + k * 128 + 4 * lane);
    const float4 bv = *(const float4*)(b12 + 4 * lane);

    for (long long i = warp * 4; i < nE; i += stride) {
        int eid[4];
        #pragma unroll
        for (int u = 0; u < 4; u++) {
            long long ii = i + u; if (ii >= nE) ii = nE - 1;
            eid[u] = __ldcs(eid_s + ii);
        }
        float ev[4];
        #pragma unroll
        for (int u = 0; u < 4; u++)
            ev[u] = __ldcs(ea + (long long)eid[u] * 16 + t16);   // MLP=4 random 64B reads

        #pragma unroll
        for (int u = 0; u < 4; u++) {
            if (i + u < nE) {
                float a0 = bv.x, a1 = bv.y, a2 = bv.z, a3 = bv.w;
                #pragma unroll
                for (int k = 0; k < 16; k++) {
                    float av = __shfl_sync(0xffffffffu, ev[u], k);
                    a0 += av * w[k].x;
                    a1 += av * w[k].y;
                    a2 += av * w[k].z;
                    a3 += av * w[k].w;
                }
                __half2 p0 = __floats2half2_rn(a0, a1);
                __half2 p1 = __floats2half2_rn(a2, a3);
                int2 pk;
                pk.x = *reinterpret_cast<int*>(&p0);
                pk.y = *reinterpret_cast<int*>(&p1);
                if (lane < 16) __stcs(reinterpret_cast<int2*>(ea1h + (i + u) * HID + 4 * lane), pk);
                else           __stcs(reinterpret_cast<int2*>(ea2h + (i + u) * HID + 4 * (lane - 16)), pk);
            }
        }
    }
}

// ---------------- streaming edge phase: segmented sum of relu(xh[src] + ea_row) ----------------
// 16 threads per chunk of EPG dst-sorted edges. (src,dst) pairs preloaded (2/thread) and
// broadcast via half-warp shfl; node features gathered fp16 (128B row = half the L2 traffic).
__global__ void __launch_bounds__(256) edge_stream_kernel(
    const __half* __restrict__ xh,    // [N,64] fp16 node features
    const __half* __restrict__ eamh,  // [E,64] sorted fp16, bias included
    const int2* __restrict__ sd,      // packed (src,dst), sorted
    float* __restrict__ agg,
    int nE)
{
    const int tid = threadIdx.x;
    const int t = tid & 15;
    const int g = tid >> 4;
    const unsigned shfl_base = (tid & 31) & 16;
    const unsigned mask = 0xFFFFu << shfl_base;

    long long base = (long long)(blockIdx.x * 16 + g) * EPG;
    if (base >= nE) return;

    // preload this chunk's 32 (src,dst) pairs: thread t holds entries 2t, 2t+1
    long long i0 = base + 2 * t;     if (i0 > (long long)nE - 1) i0 = nE - 1;
    long long i1 = i0 + 1;           if (i1 > (long long)nE - 1) i1 = nE - 1;
    int2 my0 = __ldcs(&sd[i0]);
    int2 my1 = __ldcs(&sd[i1]);

    int curd = __shfl_sync(mask, my0.y, shfl_base);
    float4 acc = make_float4(0.f, 0.f, 0.f, 0.f);

    if (base + EPG <= nE) {
        #pragma unroll
        for (int i = 0; i < EPG; i++) {
            int sx = __shfl_sync(mask, (i & 1) ? my1.x : my0.x, shfl_base + (i >> 1));
            int dy = __shfl_sync(mask, (i & 1) ? my1.y : my0.y, shfl_base + (i >> 1));
            if (dy != curd) {
                atomicAdd((float4*)(agg + (long long)curd * HID + 4 * t), acc);
                acc = make_float4(0.f, 0.f, 0.f, 0.f);
                curd = dy;
            }
            int2 raw = __ldcs(reinterpret_cast<const int2*>(eamh + (base + i) * HID + 4 * t));
            __half2 h0 = *reinterpret_cast<__half2*>(&raw.x);
            __half2 h1 = *reinterpret_cast<__half2*>(&raw.y);
            float2 e0 = __half22float2(h0);
            float2 e1 = __half22float2(h1);
            int2 xraw = *reinterpret_cast<const int2*>(xh + (long long)sx * HID + 4 * t);
            __half2 xh0 = *reinterpret_cast<__half2*>(&xraw.x);
            __half2 xh1 = *reinterpret_cast<__half2*>(&xraw.y);
            float2 x0 = __half22float2(xh0);
            float2 x1 = __half22float2(xh1);
            acc.x += fmaxf(x0.x + e0.x, 0.f);
            acc.y += fmaxf(x0.y + e0.y, 0.f);
            acc.z += fmaxf(x1.x + e1.x, 0.f);
            acc.w += fmaxf(x1.y + e1.y, 0.f);
        }
    } else {
        int cnt = (int)(nE - base);
        for (int i = 0; i < cnt; i++) {
            int sx = __shfl_sync(mask, (i & 1) ? my1.x : my0.x, shfl_base + (i >> 1));
            int dy = __shfl_sync(mask, (i & 1) ? my1.y : my0.y, shfl_base + (i >> 1));
            if (dy != curd) {
                atomicAdd((float4*)(agg + (long long)curd * HID + 4 * t), acc);
                acc = make_float4(0.f, 0.f, 0.f, 0.f);
                curd = dy;
            }
            int2 raw = __ldcs(reinterpret_cast<const int2*>(eamh + (base + i) * HID + 4 * t));
            __half2 h0 = *reinterpret_cast<__half2*>(&raw.x);
            __half2 h1 = *reinterpret_cast<__half2*>(&raw.y);
            float2 e0 = __half22float2(h0);
            float2 e1 = __half22float2(h1);
            int2 xraw = *reinterpret_cast<const int2*>(xh + (long long)sx * HID + 4 * t);
            __half2 xh0 = *reinterpret_cast<__half2*>(&xraw.x);
            __half2 xh1 = *reinterpret_cast<__half2*>(&xraw.y);
            float2 x0 = __half22float2(xh0);
            float2 x1 = __half22float2(xh1);
            acc.x += fmaxf(x0.x + e0.x, 0.f);
            acc.y += fmaxf(x0.y + e0.y, 0.f);
            acc.z += fmaxf(x1.x + e1.x, 0.f);
            acc.w += fmaxf(x1.y + e1.y, 0.f);
        }
    }
    atomicAdd((float4*)(agg + (long long)curd * HID + 4 * t), acc);
}

// ---------------- node phase (persistent): out = act(((1+eps)*x + agg) @ W + b) ----------------
template <bool RELU, bool WRITEH>
__global__ void __launch_bounds__(128) node_kernel(
    const float* __restrict__ xin,
    const float* __restrict__ agg,
    const float* __restrict__ W,     // [64,64]
    const float* __restrict__ b,
    const float* __restrict__ epsp,
    float* __restrict__ out,
    __half* __restrict__ outh,
    int nN)
{
    __shared__ float srow[8][HID];
    const int j = threadIdx.x & 63;
    const int slot = threadIdx.x >> 6;
    const float scale = 1.f + epsp[0];

    float wc[HID];
    #pragma unroll
    for (int k = 0; k < HID; k++) wc[k] = W[k * HID + j];
    const float bj = b[j];

    for (int base = blockIdx.x * 8; base < nN; base += gridDim.x * 8) {
        #pragma unroll
        for (int r = 0; r < 4; r++) {
            int n = base + slot * 4 + r;
            if (n < nN)
                srow[slot * 4 + r][j] = scale * xin[(long long)n * HID + j] + agg[(long long)n * HID + j];
        }
        __syncthreads();

        float a0 = bj, a1 = bj, a2 = bj, a3 = bj;
        #pragma unroll
        for (int k = 0; k < HID; k += 4) {
            float4 r0 = *(const float4*)&srow[slot * 4 + 0][k];
            float4 r1 = *(const float4*)&srow[slot * 4 + 1][k];
            float4 r2 = *(const float4*)&srow[slot * 4 + 2][k];
            float4 r3 = *(const float4*)&srow[slot * 4 + 3][k];
            a0 += r0.x * wc[k] + r0.y * wc[k + 1] + r0.z * wc[k + 2] + r0.w * wc[k + 3];
            a1 += r1.x * wc[k] + r1.y * wc[k + 1] + r1.z * wc[k + 2] + r1.w * wc[k + 3];
            a2 += r2.x * wc[k] + r2.y * wc[k + 1] + r2.z * wc[k + 2] + r2.w * wc[k + 3];
            a3 += r3.x * wc[k] + r3.y * wc[k + 1] + r3.z * wc[k + 2] + r3.w * wc[k + 3];
        }
        if (RELU) {
            a0 = fmaxf(a0, 0.f); a1 = fmaxf(a1, 0.f);
            a2 = fmaxf(a2, 0.f); a3 = fmaxf(a3, 0.f);
        }

        int n0 = base + slot * 4;
        if (n0 + 0 < nN) out[(long long)(n0 + 0) * HID + j] = a0;
        if (n0 + 1 < nN) out[(long long)(n0 + 1) * HID + j] = a1;
        if (n0 + 2 < nN) out[(long long)(n0 + 2) * HID + j] = a2;
        if (n0 + 3 < nN) out[(long long)(n0 + 3) * HID + j] = a3;
        if (WRITEH) {
            if (n0 + 0 < nN) outh[(long long)(n0 + 0) * HID + j] = __float2half(a0);
            if (n0 + 1 < nN) outh[(long long)(n0 + 1) * HID + j] = __float2half(a1);
            if (n0 + 2 < nN) outh[(long long)(n0 + 2) * HID + j] = __float2half(a2);
            if (n0 + 3 < nN) outh[(long long)(n0 + 3) * HID + j] = __float2half(a3);
        }
        __syncthreads();
    }
}

// ---------------- pooling: scatter-mean over sorted batch ----------------
__global__ void pool_kernel(const float* __restrict__ h,
                            const int* __restrict__ batch,
                            float* __restrict__ pooled,
                            float* __restrict__ cnt,
                            int nN)
{
    const int j = threadIdx.x & 63;
    const int p = threadIdx.x >> 6;
    const int CHUNK = 512;
    int base = blockIdx.x * CHUNK;
    int lim = base + CHUNK;
    if (lim > nN) lim = nN;

    float acc = 0.f;
    float c = 0.f;
    int curg = -1;
    for (int n = base + p; n < lim; n += 4) {
        int g = batch[n];
        if (g != curg) {
            if (curg >= 0) {
                atomicAdd(&pooled[curg * HID + j], acc);
                if (j == 0) atomicAdd(&cnt[curg], c);
            }
            acc = 0.f; c = 0.f; curg = g;
        }
        acc += h[(long long)n * HID + j];
        c += 1.f;
    }
    if (curg >= 0) {
        atomicAdd(&pooled[curg * HID + j], acc);
        if (j == 0) atomicAdd(&cnt[curg], c);
    }
}

// ---------------- head ----------------
__global__ void head_kernel(const float* __restrict__ pooled,
                            const float* __restrict__ cnt,
                            const float* __restrict__ Wm1, const float* __restrict__ bm1,
                            const float* __restrict__ Wm2, const float* __restrict__ bm2,
                            float* __restrict__ out)
{
    int gq = blockIdx.x * blockDim.x + threadIdx.x;
    if (gq >= N_GRAPHS) return;
    float inv = 1.f / fmaxf(cnt[gq], 1.f);
    float row[HID];
    #pragma unroll
    for (int k = 0; k < HID; k++) row[k] = pooled[gq * HID + k] * inv;
    float o[N_TASKS];
    #pragma unroll
    for (int ts = 0; ts < N_TASKS; ts++) o[ts] = bm2[ts];
    for (int jj = 0; jj < HID; jj++) {
        float hv = bm1[jj];
        #pragma unroll 16
        for (int k = 0; k < HID; k++) hv += row[k] * Wm1[k * HID + jj];
        hv = fmaxf(hv, 0.f);
        #pragma unroll
        for (int ts = 0; ts < N_TASKS; ts++) o[ts] += hv * Wm2[jj * N_TASKS + ts];
    }
    #pragma unroll
    for (int ts = 0; ts < N_TASKS; ts++) out[gq * N_TASKS + ts] = o[ts];
}

// ---------------- launch ----------------
extern "C" void kernel_launch(void* const* d_in, const int* in_sizes, int n_in,
                              void* d_out, int out_size) {
    const float* x         = (const float*)d_in[0];
    const int*   eidx      = (const int*)d_in[1];
    const float* edge_attr = (const float*)d_in[2];
    const int*   batch     = (const int*)d_in[3];
    const float* We1 = (const float*)d_in[4];
    const float* be1 = (const float*)d_in[5];
    const float* We2 = (const float*)d_in[6];
    const float* be2 = (const float*)d_in[7];
    const float* W1  = (const float*)d_in[8];
    const float* b1  = (const float*)d_in[9];
    const float* e1  = (const float*)d_in[10];
    const float* W2  = (const float*)d_in[11];
    const float* b2  = (const float*)d_in[12];
    const float* e2  = (const float*)d_in[13];
    const float* W3  = (const float*)d_in[14];
    const float* b3  = (const float*)d_in[15];
    const float* e3  = (const float*)d_in[16];
    const float* Wm1 = (const float*)d_in[17];
    const float* bm1 = (const float*)d_in[18];
    const float* Wm2 = (const float*)d_in[19];
    const float* bm2 = (const float*)d_in[20];
    float* out = (float*)d_out;

    int nN = in_sizes[0] / HID;       // 100000
    int nE = in_sizes[2] / 16;        // 1600000
    const int* src = eidx;
    const int* dst = eidx + nE;

    float *agg, *hA, *hB, *pooled, *cnt, *W12, *b12;
    __half *ea1h, *ea2h, *hh;
    int *hist, *cur, *offs, *bsum, *eid_s;
    int2 *sd;
    cudaGetSymbolAddress((void**)&agg,    d_agg);
    cudaGetSymbolAddress((void**)&hA,     d_hA);
    cudaGetSymbolAddress((void**)&hB,     d_hB);
    cudaGetSymbolAddress((void**)&hh,     d_hh);
    cudaGetSymbolAddress((void**)&pooled, d_pooled);
    cudaGetSymbolAddress((void**)&cnt,    d_cnt);
    cudaGetSymbolAddress((void**)&W12,    d_W12);
    cudaGetSymbolAddress((void**)&b12,    d_b12);
    cudaGetSymbolAddress((void**)&hist,   d_hist);
    cudaGetSymbolAddress((void**)&cur,    d_cur);
    cudaGetSymbolAddress((void**)&offs,   d_offs);
    cudaGetSymbolAddress((void**)&bsum,   d_bsum);
    cudaGetSymbolAddress((void**)&eid_s,  d_eid);
    cudaGetSymbolAddress((void**)&sd,     d_sd);
    cudaGetSymbolAddress((void**)&ea1h,   d_ea1h);
    cudaGetSymbolAddress((void**)&ea2h,   d_ea2h);

    const int ZB = 256;
    const int eBlocks = (nE + ZB - 1) / ZB;
    const size_t aggBytes = (size_t)nN * HID * sizeof(float);
    const int streamBlocks = (nE + 16 * EPG - 1) / (16 * EPG);
    const int scanBlocks = (nN + 1023) / 1024;
    const int NODE_GRID = 592;
    const int cvtBlocks = (nN * HID / 2 + ZB - 1) / ZB;

    prep_kernel<<<(16 * 128 + 128 + 127) / 128, 128>>>(We1, be1, We2, be2, W12, b12);

    // ---- sort edges by dst (CSR), hierarchical scan ----
    zero2_i<<<(nN + ZB - 1) / ZB, ZB>>>(hist, cur, nN);
    hist_kernel<<<eBlocks, ZB>>>(dst, hist, nE);
    scan_block_kernel<<<scanBlocks, 1024>>>(hist, offs, bsum, nN);
    scan_top_kernel<<<1, 128>>>(bsum, scanBlocks);
    scan_add_kernel<<<scanBlocks, 1024>>>(offs, bsum, nN, nE);
    scatter_kernel<<<eBlocks, ZB>>>(src, dst, offs, cur, eid_s, sd, nE);

    // ---- transform edge features once (both layers), sorted order, fp16 ----
    transform_kernel<<<1184, 256>>>(edge_attr, eid_s, W12, b12, ea1h, ea2h, nE);
    // fp16 copy of x for the gather
    cvt_h_kernel<<<cvtBlocks, ZB>>>(x, hh, nN * HID / 2);

    // ---- conv1 ----
    cudaMemsetAsync(agg, 0, aggBytes);
    edge_stream_kernel<<<streamBlocks, 256>>>(hh, ea1h, sd, agg, nE);
    node_kernel<true, true><<<NODE_GRID, 128>>>(x, agg, W1, b1, e1, hA, hh, nN);

    // ---- conv2 ----
    cudaMemsetAsync(agg, 0, aggBytes);
    edge_stream_kernel<<<streamBlocks, 256>>>(hh, ea2h, sd, agg, nE);
    node_kernel<true, true><<<NODE_GRID, 128>>>(hA, agg, W2, b2, e2, hB, hh, nN);

    // ---- conv3 ----
    cudaMemsetAsync(agg, 0, aggBytes);
    edge_stream_kernel<<<streamBlocks, 256>>>(hh, ea2h, sd, agg, nE);
    node_kernel<false, false><<<NODE_GRID, 128>>>(hB, agg, W3, b3, e3, hA, nullptr, nN);

    // ---- pooling + head ----
    cudaMemsetAsync(pooled, 0, N_GRAPHS * HID * sizeof(float));
    cudaMemsetAsync(cnt, 0, N_GRAPHS * sizeof(float));
    pool_kernel<<<(nN + 511) / 512, 256>>>(hA, batch, pooled, cnt, nN);
    head_kernel<<<1, 256>>>(pooled, cnt, Wm1, bm1, Wm2, bm2, out);
}

// round 14
// speedup vs baseline: 1.0851x; 1.0851x over previous
#include <cuda_runtime.h>
#include <cuda_fp16.h>

#define N_NODES_MAX 100000
#define NE_MAX 1600000
#define N_GRAPHS 256
#define HID 64
#define N_TASKS 10
#define EPG 32   // edges per 16-thread group chunk (dst-sorted)

// ---------------- scratch (no allocations allowed) ----------------
__device__ __align__(16) float d_agg[N_NODES_MAX * HID];
__device__ __align__(16) float d_hA[N_NODES_MAX * HID];
__device__ __align__(16) float d_hB[N_NODES_MAX * HID];
__device__ __align__(16) float d_pooled[N_GRAPHS * HID];
__device__ __align__(16) float d_cnt[N_GRAPHS];
__device__ __align__(16) float d_W12[16 * 128];   // [We1 | We1@We2]
__device__ __align__(16) float d_b12[128];        // [be1 | be1@We2+be2]
// CSR / sorted-edge scratch
__device__ int d_hist[N_NODES_MAX];
__device__ int d_cur[N_NODES_MAX];
__device__ int d_offs[N_NODES_MAX + 1];
__device__ int d_bsum[128];
__device__ int d_eid[NE_MAX];
__device__ __align__(8) int2 d_sd[NE_MAX];        // packed (src, dst) in sorted order
// transformed edge features, dst-sorted order, bias included, fp16 (205 MB each)
__device__ __align__(16) __half d_ea1h[(long long)NE_MAX * HID];
__device__ __align__(16) __half d_ea2h[(long long)NE_MAX * HID];

// ---------------- prep ----------------
__global__ void prep_kernel(const float* __restrict__ We1, const float* __restrict__ be1,
                            const float* __restrict__ We2, const float* __restrict__ be2,
                            float* __restrict__ W12, float* __restrict__ b12) {
    int idx = blockIdx.x * blockDim.x + threadIdx.x;
    if (idx < 16 * 128) {
        int k = idx >> 7, j = idx & 127;
        if (j < 64) {
            W12[idx] = We1[k * HID + j];
        } else {
            int jj = j - 64;
            float acc = 0.f;
            #pragma unroll 8
            for (int m = 0; m < HID; m++) acc += We1[k * HID + m] * We2[m * HID + jj];
            W12[idx] = acc;
        }
    } else if (idx < 16 * 128 + 128) {
        int j = idx - 16 * 128;
        if (j < 64) {
            b12[j] = be1[j];
        } else {
            int jj = j - 64;
            float acc = be2[jj];
            #pragma unroll 8
            for (int m = 0; m < HID; m++) acc += be1[m] * We2[m * HID + jj];
            b12[j] = acc;
        }
    }
}

// ---------------- CSR build ----------------
__global__ void hist_kernel(const int* __restrict__ dst, int* __restrict__ hist, int nE) {
    int e = blockIdx.x * blockDim.x + threadIdx.x;
    if (e < nE) atomicAdd(&hist[__ldcs(dst + e)], 1);
}

__global__ void scan_block_kernel(const int* __restrict__ hist, int* __restrict__ offs,
                                  int* __restrict__ bsum, int nN) {
    __shared__ int s[1024];
    int i = blockIdx.x * 1024 + threadIdx.x;
    int v = (i < nN) ? hist[i] : 0;
    s[threadIdx.x] = v;
    __syncthreads();
    for (int off = 1; off < 1024; off <<= 1) {
        int add = (threadIdx.x >= off) ? s[threadIdx.x - off] : 0;
        __syncthreads();
        s[threadIdx.x] += add;
        __syncthreads();
    }
    if (i < nN) offs[i] = s[threadIdx.x] - v;
    if (threadIdx.x == 1023) bsum[blockIdx.x] = s[1023];
}
__global__ void scan_top_kernel(int* __restrict__ bsum, int nB) {
    __shared__ int s[128];
    int v = (threadIdx.x < nB) ? bsum[threadIdx.x] : 0;
    s[threadIdx.x] = v;
    __syncthreads();
    for (int off = 1; off < 128; off <<= 1) {
        int add = (threadIdx.x >= off) ? s[threadIdx.x - off] : 0;
        __syncthreads();
        s[threadIdx.x] += add;
        __syncthreads();
    }
    if (threadIdx.x < nB) bsum[threadIdx.x] = s[threadIdx.x] - v;
}
__global__ void scan_add_kernel(int* __restrict__ offs, const int* __restrict__ bsum,
                                int nN, int nE) {
    int i = blockIdx.x * 1024 + threadIdx.x;
    if (i < nN) offs[i] += bsum[blockIdx.x];
    if (i == 0) offs[nN] = nE;
}

__global__ void scatter_kernel(const int* __restrict__ src, const int* __restrict__ dst,
                               const int* __restrict__ offs, int* __restrict__ cur,
                               int* __restrict__ eid_s, int2* __restrict__ sd, int nE) {
    int e = blockIdx.x * blockDim.x + threadIdx.x;
    if (e < nE) {
        int d = __ldcs(dst + e);
        int s = __ldcs(src + e);
        int p = atomicAdd(&cur[d], 1);
        int i = offs[d] + p;
        eid_s[i] = e;
        sd[i] = make_int2(s, d);
    }
}

// ---------------- transform: ea1h / ea2h in sorted order, fp16; 4 edges per warp-iter ----------------
__global__ void __launch_bounds__(256) transform_kernel(
    const float* __restrict__ ea,      // [E,16] original order
    const int* __restrict__ eid_s,
    const float* __restrict__ W12,     // [16,128]
    const float* __restrict__ b12,     // [128]
    __half* __restrict__ ea1h,         // [E,64] sorted
    __half* __restrict__ ea2h,         // [E,64] sorted
    int nE)
{
    const int lane = threadIdx.x & 31;
    const int t16 = lane & 15;
    long long warp = blockIdx.x * (blockDim.x >> 5) + (threadIdx.x >> 5);
    const long long stride = (long long)gridDim.x * (blockDim.x >> 5) * 4;

    float4 w[16];
    #pragma unroll
    for (int k = 0; k < 16; k++) w[k] = *(const float4*)(W12 + k * 128 + 4 * lane);
    const float4 bv = *(const float4*)(b12 + 4 * lane);

    for (long long i = warp * 4; i < nE; i += stride) {
        int eid[4];
        #pragma unroll
        for (int u = 0; u < 4; u++) {
            long long ii = i + u; if (ii >= nE) ii = nE - 1;
            eid[u] = __ldcs(eid_s + ii);
        }
        float ev[4];
        #pragma unroll
        for (int u = 0; u < 4; u++)
            ev[u] = __ldcs(ea + (long long)eid[u] * 16 + t16);   // MLP=4 random 64B reads

        #pragma unroll
        for (int u = 0; u < 4; u++) {
            if (i + u < nE) {
                float a0 = bv.x, a1 = bv.y, a2 = bv.z, a3 = bv.w;
                #pragma unroll
                for (int k = 0; k < 16; k++) {
                    float av = __shfl_sync(0xffffffffu, ev[u], k);
                    a0 += av * w[k].x;
                    a1 += av * w[k].y;
                    a2 += av * w[k].z;
                    a3 += av * w[k].w;
                }
                __half2 p0 = __floats2half2_rn(a0, a1);
                __half2 p1 = __floats2half2_rn(a2, a3);
                int2 pk;
                pk.x = *reinterpret_cast<int*>(&p0);
                pk.y = *reinterpret_cast<int*>(&p1);
                if (lane < 16) __stcs(reinterpret_cast<int2*>(ea1h + (i + u) * HID + 4 * lane), pk);
                else           __stcs(reinterpret_cast<int2*>(ea2h + (i + u) * HID + 4 * (lane - 16)), pk);
            }
        }
    }
}

// ---------------- streaming edge phase: segmented sum of relu(x[src] + ea_row) ----------------
// 16 threads per chunk of EPG dst-sorted edges. (src,dst) pairs preloaded into registers
// up-front (2 per thread, coalesced) and broadcast via half-warp shfl, so every x-load
// address is register-known -> deep MLP instead of a per-iteration pointer chase.
__global__ void __launch_bounds__(256) edge_stream_kernel(
    const float* __restrict__ xin,
    const __half* __restrict__ eamh,  // [E,64] sorted fp16, bias included
    const int2* __restrict__ sd,      // packed (src,dst), sorted
    float* __restrict__ agg,
    int nE)
{
    const int tid = threadIdx.x;
    const int t = tid & 15;
    const int g = tid >> 4;
    const unsigned shfl_base = (tid & 31) & 16;
    const unsigned mask = 0xFFFFu << shfl_base;

    long long base = (long long)(blockIdx.x * 16 + g) * EPG;
    if (base >= nE) return;

    // preload this chunk's 32 (src,dst) pairs: thread t holds entries 2t, 2t+1
    long long i0 = base + 2 * t;     if (i0 > (long long)nE - 1) i0 = nE - 1;
    long long i1 = i0 + 1;           if (i1 > (long long)nE - 1) i1 = nE - 1;
    int2 my0 = __ldcs(&sd[i0]);
    int2 my1 = __ldcs(&sd[i1]);

    int curd = __shfl_sync(mask, my0.y, shfl_base);   // dst of entry 0
    float4 acc = make_float4(0.f, 0.f, 0.f, 0.f);

    if (base + EPG <= nE) {
        #pragma unroll
        for (int i = 0; i < EPG; i++) {
            int sx = __shfl_sync(mask, (i & 1) ? my1.x : my0.x, shfl_base + (i >> 1));
            int dy = __shfl_sync(mask, (i & 1) ? my1.y : my0.y, shfl_base + (i >> 1));
            if (dy != curd) {
                atomicAdd((float4*)(agg + (long long)curd * HID + 4 * t), acc);
                acc = make_float4(0.f, 0.f, 0.f, 0.f);
                curd = dy;
            }
            int2 raw = __ldcs(reinterpret_cast<const int2*>(eamh + (base + i) * HID + 4 * t));
            __half2 h0 = *reinterpret_cast<__half2*>(&raw.x);
            __half2 h1 = *reinterpret_cast<__half2*>(&raw.y);
            float2 e0 = __half22float2(h0);
            float2 e1 = __half22float2(h1);
            float4 xv = *(const float4*)(xin + (long long)sx * HID + 4 * t);
            acc.x += fmaxf(xv.x + e0.x, 0.f);
            acc.y += fmaxf(xv.y + e0.y, 0.f);
            acc.z += fmaxf(xv.z + e1.x, 0.f);
            acc.w += fmaxf(xv.w + e1.y, 0.f);
        }
    } else {
        int cnt = (int)(nE - base);
        for (int i = 0; i < cnt; i++) {
            int sx = __shfl_sync(mask, (i & 1) ? my1.x : my0.x, shfl_base + (i >> 1));
            int dy = __shfl_sync(mask, (i & 1) ? my1.y : my0.y, shfl_base + (i >> 1));
            if (dy != curd) {
                atomicAdd((float4*)(agg + (long long)curd * HID + 4 * t), acc);
                acc = make_float4(0.f, 0.f, 0.f, 0.f);
                curd = dy;
            }
            int2 raw = __ldcs(reinterpret_cast<const int2*>(eamh + (base + i) * HID + 4 * t));
            __half2 h0 = *reinterpret_cast<__half2*>(&raw.x);
            __half2 h1 = *reinterpret_cast<__half2*>(&raw.y);
            float2 e0 = __half22float2(h0);
            float2 e1 = __half22float2(h1);
            float4 xv = *(const float4*)(xin + (long long)sx * HID + 4 * t);
            acc.x += fmaxf(xv.x + e0.x, 0.f);
            acc.y += fmaxf(xv.y + e0.y, 0.f);
            acc.z += fmaxf(xv.z + e1.x, 0.f);
            acc.w += fmaxf(xv.w + e1.y, 0.f);
        }
    }
    atomicAdd((float4*)(agg + (long long)curd * HID + 4 * t), acc);
}

// ---------------- node phase (persistent) ----------------
template <bool RELU>
__global__ void __launch_bounds__(128) node_kernel(
    const float* __restrict__ xin,
    const float* __restrict__ agg,
    const float* __restrict__ W,     // [64,64]
    const float* __restrict__ b,
    const float* __restrict__ epsp,
    float* __restrict__ out,
    int nN)
{
    __shared__ float srow[8][HID];
    const int j = threadIdx.x & 63;
    const int slot = threadIdx.x >> 6;
    const float scale = 1.f + epsp[0];

    float wc[HID];
    #pragma unroll
    for (int k = 0; k < HID; k++) wc[k] = W[k * HID + j];
    const float bj = b[j];

    for (int base = blockIdx.x * 8; base < nN; base += gridDim.x * 8) {
        #pragma unroll
        for (int r = 0; r < 4; r++) {
            int n = base + slot * 4 + r;
            if (n < nN)
                srow[slot * 4 + r][j] = scale * xin[(long long)n * HID + j] + agg[(long long)n * HID + j];
        }
        __syncthreads();

        float a0 = bj, a1 = bj, a2 = bj, a3 = bj;
        #pragma unroll
        for (int k = 0; k < HID; k += 4) {
            float4 r0 = *(const float4*)&srow[slot * 4 + 0][k];
            float4 r1 = *(const float4*)&srow[slot * 4 + 1][k];
            float4 r2 = *(const float4*)&srow[slot * 4 + 2][k];
            float4 r3 = *(const float4*)&srow[slot * 4 + 3][k];
            a0 += r0.x * wc[k] + r0.y * wc[k + 1] + r0.z * wc[k + 2] + r0.w * wc[k + 3];
            a1 += r1.x * wc[k] + r1.y * wc[k + 1] + r1.z * wc[k + 2] + r1.w * wc[k + 3];
            a2 += r2.x * wc[k] + r2.y * wc[k + 1] + r2.z * wc[k + 2] + r2.w * wc[k + 3];
            a3 += r3.x * wc[k] + r3.y * wc[k + 1] + r3.z * wc[k + 2] + r3.w * wc[k + 3];
        }

        int n0 = base + slot * 4;
        if (n0 + 0 < nN) out[(long long)(n0 + 0) * HID + j] = RELU ? fmaxf(a0, 0.f) : a0;
        if (n0 + 1 < nN) out[(long long)(n0 + 1) * HID + j] = RELU ? fmaxf(a1, 0.f) : a1;
        if (n0 + 2 < nN) out[(long long)(n0 + 2) * HID + j] = RELU ? fmaxf(a2, 0.f) : a2;
        if (n0 + 3 < nN) out[(long long)(n0 + 3) * HID + j] = RELU ? fmaxf(a3, 0.f) : a3;
        __syncthreads();
    }
}

// ---------------- pooling: scatter-mean over sorted batch ----------------
__global__ void pool_kernel(const float* __restrict__ h,
                            const int* __restrict__ batch,
                            float* __restrict__ pooled,
                            float* __restrict__ cnt,
                            int nN)
{
    const int j = threadIdx.x & 63;
    const int p = threadIdx.x >> 6;
    const int CHUNK = 512;
    int base = blockIdx.x * CHUNK;
    int lim = base + CHUNK;
    if (lim > nN) lim = nN;

    float acc = 0.f;
    float c = 0.f;
    int curg = -1;
    for (int n = base + p; n < lim; n += 4) {
        int g = batch[n];
        if (g != curg) {
            if (curg >= 0) {
                atomicAdd(&pooled[curg * HID + j], acc);
                if (j == 0) atomicAdd(&cnt[curg], c);
            }
            acc = 0.f; c = 0.f; curg = g;
        }
        acc += h[(long long)n * HID + j];
        c += 1.f;
    }
    if (curg >= 0) {
        atomicAdd(&pooled[curg * HID + j], acc);
        if (j == 0) atomicAdd(&cnt[curg], c);
    }
}

// ---------------- head ----------------
__global__ void head_kernel(const float* __restrict__ pooled,
                            const float* __restrict__ cnt,
                            const float* __restrict__ Wm1, const float* __restrict__ bm1,
                            const float* __restrict__ Wm2, const float* __restrict__ bm2,
                            float* __restrict__ out)
{
    int gq = blockIdx.x * blockDim.x + threadIdx.x;
    if (gq >= N_GRAPHS) return;
    float inv = 1.f / fmaxf(cnt[gq], 1.f);
    float row[HID];
    #pragma unroll
    for (int k = 0; k < HID; k++) row[k] = pooled[gq * HID + k] * inv;
    float o[N_TASKS];
    #pragma unroll
    for (int ts = 0; ts < N_TASKS; ts++) o[ts] = bm2[ts];
    for (int jj = 0; jj < HID; jj++) {
        float hv = bm1[jj];
        #pragma unroll 16
        for (int k = 0; k < HID; k++) hv += row[k] * Wm1[k * HID + jj];
        hv = fmaxf(hv, 0.f);
        #pragma unroll
        for (int ts = 0; ts < N_TASKS; ts++) o[ts] += hv * Wm2[jj * N_TASKS + ts];
    }
    #pragma unroll
    for (int ts = 0; ts < N_TASKS; ts++) out[gq * N_TASKS + ts] = o[ts];
}

// ---------------- launch ----------------
extern "C" void kernel_launch(void* const* d_in, const int* in_sizes, int n_in,
                              void* d_out, int out_size) {
    const float* x         = (const float*)d_in[0];
    const int*   eidx      = (const int*)d_in[1];
    const float* edge_attr = (const float*)d_in[2];
    const int*   batch     = (const int*)d_in[3];
    const float* We1 = (const float*)d_in[4];
    const float* be1 = (const float*)d_in[5];
    const float* We2 = (const float*)d_in[6];
    const float* be2 = (const float*)d_in[7];
    const float* W1  = (const float*)d_in[8];
    const float* b1  = (const float*)d_in[9];
    const float* e1  = (const float*)d_in[10];
    const float* W2  = (const float*)d_in[11];
    const float* b2  = (const float*)d_in[12];
    const float* e2  = (const float*)d_in[13];
    const float* W3  = (const float*)d_in[14];
    const float* b3  = (const float*)d_in[15];
    const float* e3  = (const float*)d_in[16];
    const float* Wm1 = (const float*)d_in[17];
    const float* bm1 = (const float*)d_in[18];
    const float* Wm2 = (const float*)d_in[19];
    const float* bm2 = (const float*)d_in[20];
    float* out = (float*)d_out;

    int nN = in_sizes[0] / HID;       // 100000
    int nE = in_sizes[2] / 16;        // 1600000
    const int* src = eidx;
    const int* dst = eidx + nE;

    float *agg, *hA, *hB, *pooled, *cnt, *W12, *b12;
    __half *ea1h, *ea2h;
    int *hist, *cur, *offs, *bsum, *eid_s;
    int2 *sd;
    cudaGetSymbolAddress((void**)&agg,    d_agg);
    cudaGetSymbolAddress((void**)&hA,     d_hA);
    cudaGetSymbolAddress((void**)&hB,     d_hB);
    cudaGetSymbolAddress((void**)&pooled, d_pooled);
    cudaGetSymbolAddress((void**)&cnt,    d_cnt);
    cudaGetSymbolAddress((void**)&W12,    d_W12);
    cudaGetSymbolAddress((void**)&b12,    d_b12);
    cudaGetSymbolAddress((void**)&hist,   d_hist);
    cudaGetSymbolAddress((void**)&cur,    d_cur);
    cudaGetSymbolAddress((void**)&offs,   d_offs);
    cudaGetSymbolAddress((void**)&bsum,   d_bsum);
    cudaGetSymbolAddress((void**)&eid_s,  d_eid);
    cudaGetSymbolAddress((void**)&sd,     d_sd);
    cudaGetSymbolAddress((void**)&ea1h,   d_ea1h);
    cudaGetSymbolAddress((void**)&ea2h,   d_ea2h);

    const int ZB = 256;
    const int eBlocks = (nE + ZB - 1) / ZB;
    const size_t aggBytes = (size_t)nN * HID * sizeof(float);
    const int streamBlocks = (nE + 16 * EPG - 1) / (16 * EPG);
    const int scanBlocks = (nN + 1023) / 1024;
    const int NODE_GRID = 592;

    prep_kernel<<<(16 * 128 + 128 + 127) / 128, 128>>>(We1, be1, We2, be2, W12, b12);

    // ---- sort edges by dst (CSR), hierarchical scan ----
    cudaMemsetAsync(hist, 0, (size_t)nN * sizeof(int));
    cudaMemsetAsync(cur,  0, (size_t)nN * sizeof(int));
    hist_kernel<<<eBlocks, ZB>>>(dst, hist, nE);
    scan_block_kernel<<<scanBlocks, 1024>>>(hist, offs, bsum, nN);
    scan_top_kernel<<<1, 128>>>(bsum, scanBlocks);
    scan_add_kernel<<<scanBlocks, 1024>>>(offs, bsum, nN, nE);
    scatter_kernel<<<eBlocks, ZB>>>(src, dst, offs, cur, eid_s, sd, nE);

    // ---- transform edge features once (both layers), sorted order, fp16 ----
    transform_kernel<<<1184, 256>>>(edge_attr, eid_s, W12, b12, ea1h, ea2h, nE);

    // ---- conv1 ----
    cudaMemsetAsync(agg, 0, aggBytes);
    edge_stream_kernel<<<streamBlocks, 256>>>(x, ea1h, sd, agg, nE);
    node_kernel<true><<<NODE_GRID, 128>>>(x, agg, W1, b1, e1, hA, nN);

    // ---- conv2 ----
    cudaMemsetAsync(agg, 0, aggBytes);
    edge_stream_kernel<<<streamBlocks, 256>>>(hA, ea2h, sd, agg, nE);
    node_kernel<true><<<NODE_GRID, 128>>>(hA, agg, W2, b2, e2, hB, nN);

    // ---- conv3 ----
    cudaMemsetAsync(agg, 0, aggBytes);
    edge_stream_kernel<<<streamBlocks, 256>>>(hB, ea2h, sd, agg, nE);
    node_kernel<false><<<NODE_GRID, 128>>>(hB, agg, W3, b3, e3, hA, nN);

    // ---- pooling + head ----
    cudaMemsetAsync(pooled, 0, N_GRAPHS * HID * sizeof(float));
    cudaMemsetAsync(cnt, 0, N_GRAPHS * sizeof(float));
    pool_kernel<<<(nN + 511) / 512, 256>>>(hA, batch, pooled, cnt, nN);
    head_kernel<<<1, 256>>>(pooled, cnt, Wm1, bm1, Wm2, bm2, out);
}

// round 16
// speedup vs baseline: 1.1658x; 1.0744x over previous
#include <cuda_runtime.h>
#include <cuda_fp16.h>

#define N_NODES_MAX 100000
#define NE_MAX 1600000
#define N_GRAPHS 256
#define HID 64
#define N_TASKS 10
#define EPG 32   // edges per 16-thread group chunk (dst-sorted)

// ---------------- scratch (no allocations allowed) ----------------
__device__ __align__(16) float d_agg[N_NODES_MAX * HID];
__device__ __align__(16) float d_hA[N_NODES_MAX * HID];
__device__ __align__(16) float d_hB[N_NODES_MAX * HID];
__device__ __align__(16) float d_pooled[N_GRAPHS * HID];
__device__ __align__(16) float d_cnt[N_GRAPHS];
__device__ __align__(16) float d_W12[16 * 128];   // [We1 | We1@We2]
__device__ __align__(16) float d_b12[128];        // [be1 | be1@We2+be2]
// CSR / sorted-edge scratch
__device__ int d_hist[N_NODES_MAX];
__device__ int d_cur[N_NODES_MAX];
__device__ int d_offs[N_NODES_MAX + 1];
__device__ int d_bsum[128];
__device__ int d_pos[NE_MAX];                     // pos[e] = sorted position of edge e
__device__ __align__(8) int2 d_sd[NE_MAX];        // packed (src, dst) in sorted order
// transformed edge features, dst-sorted order, bias included, fp16 (205 MB each)
__device__ __align__(16) __half d_ea1h[(long long)NE_MAX * HID];
__device__ __align__(16) __half d_ea2h[(long long)NE_MAX * HID];

// ---------------- prep ----------------
__global__ void prep_kernel(const float* __restrict__ We1, const float* __restrict__ be1,
                            const float* __restrict__ We2, const float* __restrict__ be2,
                            float* __restrict__ W12, float* __restrict__ b12) {
    int idx = blockIdx.x * blockDim.x + threadIdx.x;
    if (idx < 16 * 128) {
        int k = idx >> 7, j = idx & 127;
        if (j < 64) {
            W12[idx] = We1[k * HID + j];
        } else {
            int jj = j - 64;
            float acc = 0.f;
            #pragma unroll 8
            for (int m = 0; m < HID; m++) acc += We1[k * HID + m] * We2[m * HID + jj];
            W12[idx] = acc;
        }
    } else if (idx < 16 * 128 + 128) {
        int j = idx - 16 * 128;
        if (j < 64) {
            b12[j] = be1[j];
        } else {
            int jj = j - 64;
            float acc = be2[jj];
            #pragma unroll 8
            for (int m = 0; m < HID; m++) acc += be1[m] * We2[m * HID + jj];
            b12[j] = acc;
        }
    }
}

// ---------------- CSR build ----------------
__global__ void hist_kernel(const int* __restrict__ dst, int* __restrict__ hist, int nE) {
    int e = blockIdx.x * blockDim.x + threadIdx.x;
    if (e < nE) atomicAdd(&hist[__ldcs(dst + e)], 1);
}

__global__ void scan_block_kernel(const int* __restrict__ hist, int* __restrict__ offs,
                                  int* __restrict__ bsum, int nN) {
    __shared__ int s[1024];
    int i = blockIdx.x * 1024 + threadIdx.x;
    int v = (i < nN) ? hist[i] : 0;
    s[threadIdx.x] = v;
    __syncthreads();
    for (int off = 1; off < 1024; off <<= 1) {
        int add = (threadIdx.x >= off) ? s[threadIdx.x - off] : 0;
        __syncthreads();
        s[threadIdx.x] += add;
        __syncthreads();
    }
    if (i < nN) offs[i] = s[threadIdx.x] - v;
    if (threadIdx.x == 1023) bsum[blockIdx.x] = s[1023];
}
__global__ void scan_top_kernel(int* __restrict__ bsum, int nB) {
    __shared__ int s[128];
    int v = (threadIdx.x < nB) ? bsum[threadIdx.x] : 0;
    s[threadIdx.x] = v;
    __syncthreads();
    for (int off = 1; off < 128; off <<= 1) {
        int add = (threadIdx.x >= off) ? s[threadIdx.x - off] : 0;
        __syncthreads();
        s[threadIdx.x] += add;
        __syncthreads();
    }
    if (threadIdx.x < nB) bsum[threadIdx.x] = s[threadIdx.x] - v;
}
__global__ void scan_add_kernel(int* __restrict__ offs, const int* __restrict__ bsum,
                                int nN, int nE) {
    int i = blockIdx.x * 1024 + threadIdx.x;
    if (i < nN) offs[i] += bsum[blockIdx.x];
    if (i == 0) offs[nN] = nE;
}

// also records pos[e] = sorted slot of edge e (inverse permutation)
__global__ void scatter_kernel(const int* __restrict__ src, const int* __restrict__ dst,
                               const int* __restrict__ offs, int* __restrict__ cur,
                               int* __restrict__ pos, int2* __restrict__ sd, int nE) {
    int e = blockIdx.x * blockDim.x + threadIdx.x;
    if (e < nE) {
        int d = __ldcs(dst + e);
        int s = __ldcs(src + e);
        int p = atomicAdd(&cur[d], 1);
        int i = offs[d] + p;
        pos[e] = i;
        sd[i] = make_int2(s, d);
    }
}

// ---------------- transform (original order in, scattered full-line writes out) ----------------
// One warp per edge, 4 edges per iteration. ea reads are fully coalesced streams;
// outputs scatter to sorted position pos[e] as complete 128B lines (no RMW, no read latency).
__global__ void __launch_bounds__(256) transform_kernel(
    const float* __restrict__ ea,      // [E,16] original order (streamed)
    const int* __restrict__ pos,       // [E] sorted position per edge (streamed)
    const float* __restrict__ W12,     // [16,128]
    const float* __restrict__ b12,     // [128]
    __half* __restrict__ ea1h,         // [E,64] sorted
    __half* __restrict__ ea2h,         // [E,64] sorted
    int nE)
{
    const int lane = threadIdx.x & 31;
    const int t16 = lane & 15;
    long long warp = blockIdx.x * (blockDim.x >> 5) + (threadIdx.x >> 5);
    const long long stride = (long long)gridDim.x * (blockDim.x >> 5) * 4;

    float4 w[16];
    #pragma unroll
    for (int k = 0; k < 16; k++) w[k] = *(const float4*)(W12 + k * 128 + 4 * lane);
    const float4 bv = *(const float4*)(b12 + 4 * lane);

    for (long long i = warp * 4; i < nE; i += stride) {
        float ev[4];
        int ps[4];
        #pragma unroll
        for (int u = 0; u < 4; u++) {
            long long e = i + u; if (e >= nE) e = nE - 1;
            ev[u] = __ldcs(ea + e * 16 + t16);   // sequential, coalesced
            ps[u] = __ldcs(pos + e);             // sequential, broadcast across warp
        }

        #pragma unroll
        for (int u = 0; u < 4; u++) {
            if (i + u < nE) {
                float a0 = bv.x, a1 = bv.y, a2 = bv.z, a3 = bv.w;
                #pragma unroll
                for (int k = 0; k < 16; k++) {
                    float av = __shfl_sync(0xffffffffu, ev[u], k);
                    a0 += av * w[k].x;
                    a1 += av * w[k].y;
                    a2 += av * w[k].z;
                    a3 += av * w[k].w;
                }
                __half2 p0 = __floats2half2_rn(a0, a1);
                __half2 p1 = __floats2half2_rn(a2, a3);
                int2 pk;
                pk.x = *reinterpret_cast<int*>(&p0);
                pk.y = *reinterpret_cast<int*>(&p1);
                long long row = (long long)ps[u] * HID;
                if (lane < 16) __stcs(reinterpret_cast<int2*>(ea1h + row + 4 * lane), pk);
                else           __stcs(reinterpret_cast<int2*>(ea2h + row + 4 * (lane - 16)), pk);
            }
        }
    }
}

// ---------------- streaming edge phase: segmented sum of relu(x[src] + ea_row) ----------------
// 16 threads per chunk of EPG dst-sorted edges. (src,dst) pairs preloaded into registers
// up-front (2 per thread, coalesced) and broadcast via half-warp shfl.
__global__ void __launch_bounds__(256) edge_stream_kernel(
    const float* __restrict__ xin,
    const __half* __restrict__ eamh,  // [E,64] sorted fp16, bias included
    const int2* __restrict__ sd,      // packed (src,dst), sorted
    float* __restrict__ agg,
    int nE)
{
    const int tid = threadIdx.x;
    const int t = tid & 15;
    const int g = tid >> 4;
    const unsigned shfl_base = (tid & 31) & 16;
    const unsigned mask = 0xFFFFu << shfl_base;

    long long base = (long long)(blockIdx.x * 16 + g) * EPG;
    if (base >= nE) return;

    long long i0 = base + 2 * t;     if (i0 > (long long)nE - 1) i0 = nE - 1;
    long long i1 = i0 + 1;           if (i1 > (long long)nE - 1) i1 = nE - 1;
    int2 my0 = __ldcs(&sd[i0]);
    int2 my1 = __ldcs(&sd[i1]);

    int curd = __shfl_sync(mask, my0.y, shfl_base);
    float4 acc = make_float4(0.f, 0.f, 0.f, 0.f);

    if (base + EPG <= nE) {
        #pragma unroll
        for (int i = 0; i < EPG; i++) {
            int sx = __shfl_sync(mask, (i & 1) ? my1.x : my0.x, shfl_base + (i >> 1));
            int dy = __shfl_sync(mask, (i & 1) ? my1.y : my0.y, shfl_base + (i >> 1));
            if (dy != curd) {
                atomicAdd((float4*)(agg + (long long)curd * HID + 4 * t), acc);
                acc = make_float4(0.f, 0.f, 0.f, 0.f);
                curd = dy;
            }
            int2 raw = __ldcs(reinterpret_cast<const int2*>(eamh + (base + i) * HID + 4 * t));
            __half2 h0 = *reinterpret_cast<__half2*>(&raw.x);
            __half2 h1 = *reinterpret_cast<__half2*>(&raw.y);
            float2 e0 = __half22float2(h0);
            float2 e1 = __half22float2(h1);
            float4 xv = *(const float4*)(xin + (long long)sx * HID + 4 * t);
            acc.x += fmaxf(xv.x + e0.x, 0.f);
            acc.y += fmaxf(xv.y + e0.y, 0.f);
            acc.z += fmaxf(xv.z + e1.x, 0.f);
            acc.w += fmaxf(xv.w + e1.y, 0.f);
        }
    } else {
        int cnt = (int)(nE - base);
        for (int i = 0; i < cnt; i++) {
            int sx = __shfl_sync(mask, (i & 1) ? my1.x : my0.x, shfl_base + (i >> 1));
            int dy = __shfl_sync(mask, (i & 1) ? my1.y : my0.y, shfl_base + (i >> 1));
            if (dy != curd) {
                atomicAdd((float4*)(agg + (long long)curd * HID + 4 * t), acc);
                acc = make_float4(0.f, 0.f, 0.f, 0.f);
                curd = dy;
            }
            int2 raw = __ldcs(reinterpret_cast<const int2*>(eamh + (base + i) * HID + 4 * t));
            __half2 h0 = *reinterpret_cast<__half2*>(&raw.x);
            __half2 h1 = *reinterpret_cast<__half2*>(&raw.y);
            float2 e0 = __half22float2(h0);
            float2 e1 = __half22float2(h1);
            float4 xv = *(const float4*)(xin + (long long)sx * HID + 4 * t);
            acc.x += fmaxf(xv.x + e0.x, 0.f);
            acc.y += fmaxf(xv.y + e0.y, 0.f);
            acc.z += fmaxf(xv.z + e1.x, 0.f);
            acc.w += fmaxf(xv.w + e1.y, 0.f);
        }
    }
    atomicAdd((float4*)(agg + (long long)curd * HID + 4 * t), acc);
}

// ---------------- node phase (persistent) ----------------
template <bool RELU>
__global__ void __launch_bounds__(128) node_kernel(
    const float* __restrict__ xin,
    const float* __restrict__ agg,
    const float* __restrict__ W,     // [64,64]
    const float* __restrict__ b,
    const float* __restrict__ epsp,
    float* __restrict__ out,
    int nN)
{
    __shared__ float srow[8][HID];
    const int j = threadIdx.x & 63;
    const int slot = threadIdx.x >> 6;
    const float scale = 1.f + epsp[0];

    float wc[HID];
    #pragma unroll
    for (int k = 0; k < HID; k++) wc[k] = W[k * HID + j];
    const float bj = b[j];

    for (int base = blockIdx.x * 8; base < nN; base += gridDim.x * 8) {
        #pragma unroll
        for (int r = 0; r < 4; r++) {
            int n = base + slot * 4 + r;
            if (n < nN)
                srow[slot * 4 + r][j] = scale * xin[(long long)n * HID + j] + agg[(long long)n * HID + j];
        }
        __syncthreads();

        float a0 = bj, a1 = bj, a2 = bj, a3 = bj;
        #pragma unroll
        for (int k = 0; k < HID; k += 4) {
            float4 r0 = *(const float4*)&srow[slot * 4 + 0][k];
            float4 r1 = *(const float4*)&srow[slot * 4 + 1][k];
            float4 r2 = *(const float4*)&srow[slot * 4 + 2][k];
            float4 r3 = *(const float4*)&srow[slot * 4 + 3][k];
            a0 += r0.x * wc[k] + r0.y * wc[k + 1] + r0.z * wc[k + 2] + r0.w * wc[k + 3];
            a1 += r1.x * wc[k] + r1.y * wc[k + 1] + r1.z * wc[k + 2] + r1.w * wc[k + 3];
            a2 += r2.x * wc[k] + r2.y * wc[k + 1] + r2.z * wc[k + 2] + r2.w * wc[k + 3];
            a3 += r3.x * wc[k] + r3.y * wc[k + 1] + r3.z * wc[k + 2] + r3.w * wc[k + 3];
        }

        int n0 = base + slot * 4;
        if (n0 + 0 < nN) out[(long long)(n0 + 0) * HID + j] = RELU ? fmaxf(a0, 0.f) : a0;
        if (n0 + 1 < nN) out[(long long)(n0 + 1) * HID + j] = RELU ? fmaxf(a1, 0.f) : a1;
        if (n0 + 2 < nN) out[(long long)(n0 + 2) * HID + j] = RELU ? fmaxf(a2, 0.f) : a2;
        if (n0 + 3 < nN) out[(long long)(n0 + 3) * HID + j] = RELU ? fmaxf(a3, 0.f) : a3;
        __syncthreads();
    }
}

// ---------------- pooling: scatter-mean over sorted batch ----------------
__global__ void pool_kernel(const float* __restrict__ h,
                            const int* __restrict__ batch,
                            float* __restrict__ pooled,
                            float* __restrict__ cnt,
                            int nN)
{
    const int j = threadIdx.x & 63;
    const int p = threadIdx.x >> 6;
    const int CHUNK = 512;
    int base = blockIdx.x * CHUNK;
    int lim = base + CHUNK;
    if (lim > nN) lim = nN;

    float acc = 0.f;
    float c = 0.f;
    int curg = -1;
    for (int n = base + p; n < lim; n += 4) {
        int g = batch[n];
        if (g != curg) {
            if (curg >= 0) {
                atomicAdd(&pooled[curg * HID + j], acc);
                if (j == 0) atomicAdd(&cnt[curg], c);
            }
            acc = 0.f; c = 0.f; curg = g;
        }
        acc += h[(long long)n * HID + j];
        c += 1.f;
    }
    if (curg >= 0) {
        atomicAdd(&pooled[curg * HID + j], acc);
        if (j == 0) atomicAdd(&cnt[curg], c);
    }
}

// ---------------- head ----------------
__global__ void head_kernel(const float* __restrict__ pooled,
                            const float* __restrict__ cnt,
                            const float* __restrict__ Wm1, const float* __restrict__ bm1,
                            const float* __restrict__ Wm2, const float* __restrict__ bm2,
                            float* __restrict__ out)
{
    int gq = blockIdx.x * blockDim.x + threadIdx.x;
    if (gq >= N_GRAPHS) return;
    float inv = 1.f / fmaxf(cnt[gq], 1.f);
    float row[HID];
    #pragma unroll
    for (int k = 0; k < HID; k++) row[k] = pooled[gq * HID + k] * inv;
    float o[N_TASKS];
    #pragma unroll
    for (int ts = 0; ts < N_TASKS; ts++) o[ts] = bm2[ts];
    for (int jj = 0; jj < HID; jj++) {
        float hv = bm1[jj];
        #pragma unroll 16
        for (int k = 0; k < HID; k++) hv += row[k] * Wm1[k * HID + jj];
        hv = fmaxf(hv, 0.f);
        #pragma unroll
        for (int ts = 0; ts < N_TASKS; ts++) o[ts] += hv * Wm2[jj * N_TASKS + ts];
    }
    #pragma unroll
    for (int ts = 0; ts < N_TASKS; ts++) out[gq * N_TASKS + ts] = o[ts];
}

// ---------------- launch ----------------
extern "C" void kernel_launch(void* const* d_in, const int* in_sizes, int n_in,
                              void* d_out, int out_size) {
    const float* x         = (const float*)d_in[0];
    const int*   eidx      = (const int*)d_in[1];
    const float* edge_attr = (const float*)d_in[2];
    const int*   batch     = (const int*)d_in[3];
    const float* We1 = (const float*)d_in[4];
    const float* be1 = (const float*)d_in[5];
    const float* We2 = (const float*)d_in[6];
    const float* be2 = (const float*)d_in[7];
    const float* W1  = (const float*)d_in[8];
    const float* b1  = (const float*)d_in[9];
    const float* e1  = (const float*)d_in[10];
    const float* W2  = (const float*)d_in[11];
    const float* b2  = (const float*)d_in[12];
    const float* e2  = (const float*)d_in[13];
    const float* W3  = (const float*)d_in[14];
    const float* b3  = (const float*)d_in[15];
    const float* e3  = (const float*)d_in[16];
    const float* Wm1 = (const float*)d_in[17];
    const float* bm1 = (const float*)d_in[18];
    const float* Wm2 = (const float*)d_in[19];
    const float* bm2 = (const float*)d_in[20];
    float* out = (float*)d_out;

    int nN = in_sizes[0] / HID;       // 100000
    int nE = in_sizes[2] / 16;        // 1600000
    const int* src = eidx;
    const int* dst = eidx + nE;

    float *agg, *hA, *hB, *pooled, *cnt, *W12, *b12;
    __half *ea1h, *ea2h;
    int *hist, *cur, *offs, *bsum, *pos;
    int2 *sd;
    cudaGetSymbolAddress((void**)&agg,    d_agg);
    cudaGetSymbolAddress((void**)&hA,     d_hA);
    cudaGetSymbolAddress((void**)&hB,     d_hB);
    cudaGetSymbolAddress((void**)&pooled, d_pooled);
    cudaGetSymbolAddress((void**)&cnt,    d_cnt);
    cudaGetSymbolAddress((void**)&W12,    d_W12);
    cudaGetSymbolAddress((void**)&b12,    d_b12);
    cudaGetSymbolAddress((void**)&hist,   d_hist);
    cudaGetSymbolAddress((void**)&cur,    d_cur);
    cudaGetSymbolAddress((void**)&offs,   d_offs);
    cudaGetSymbolAddress((void**)&bsum,   d_bsum);
    cudaGetSymbolAddress((void**)&pos,    d_pos);
    cudaGetSymbolAddress((void**)&sd,     d_sd);
    cudaGetSymbolAddress((void**)&ea1h,   d_ea1h);
    cudaGetSymbolAddress((void**)&ea2h,   d_ea2h);

    const int ZB = 256;
    const int eBlocks = (nE + ZB - 1) / ZB;
    const size_t aggBytes = (size_t)nN * HID * sizeof(float);
    const int streamBlocks = (nE + 16 * EPG - 1) / (16 * EPG);
    const int scanBlocks = (nN + 1023) / 1024;
    const int NODE_GRID = 592;

    prep_kernel<<<(16 * 128 + 128 + 127) / 128, 128>>>(We1, be1, We2, be2, W12, b12);

    // ---- sort edges by dst (CSR), hierarchical scan ----
    cudaMemsetAsync(hist, 0, (size_t)nN * sizeof(int));
    cudaMemsetAsync(cur,  0, (size_t)nN * sizeof(int));
    hist_kernel<<<eBlocks, ZB>>>(dst, hist, nE);
    scan_block_kernel<<<scanBlocks, 1024>>>(hist, offs, bsum, nN);
    scan_top_kernel<<<1, 128>>>(bsum, scanBlocks);
    scan_add_kernel<<<scanBlocks, 1024>>>(offs, bsum, nN, nE);
    scatter_kernel<<<eBlocks, ZB>>>(src, dst, offs, cur, pos, sd, nE);

    // ---- transform: stream ea in original order, scatter full-line fp16 outputs ----
    transform_kernel<<<1184, 256>>>(edge_attr, pos, W12, b12, ea1h, ea2h, nE);

    // ---- conv1 ----
    cudaMemsetAsync(agg, 0, aggBytes);
    edge_stream_kernel<<<streamBlocks, 256>>>(x, ea1h, sd, agg, nE);
    node_kernel<true><<<NODE_GRID, 128>>>(x, agg, W1, b1, e1, hA, nN);

    // ---- conv2 ----
    cudaMemsetAsync(agg, 0, aggBytes);
    edge_stream_kernel<<<streamBlocks, 256>>>(hA, ea2h, sd, agg, nE);
    node_kernel<true><<<NODE_GRID, 128>>>(hA, agg, W2, b2, e2, hB, nN);

    // ---- conv3 ----
    cudaMemsetAsync(agg, 0, aggBytes);
    edge_stream_kernel<<<streamBlocks, 256>>>(hB, ea2h, sd, agg, nE);
    node_kernel<false><<<NODE_GRID, 128>>>(hB, agg, W3, b3, e3, hA, nN);

    // ---- pooling + head ----
    cudaMemsetAsync(pooled, 0, N_GRAPHS * HID * sizeof(float));
    cudaMemsetAsync(cnt, 0, N_GRAPHS * sizeof(float));
    pool_kernel<<<(nN + 511) / 512, 256>>>(hA, batch, pooled, cnt, nN);
    head_kernel<<<1, 256>>>(pooled, cnt, Wm1, bm1, Wm2, bm2, out);
}

// round 17
// speedup vs baseline: 1.2534x; 1.0752x over previous
#include <cuda_runtime.h>
#include <cuda_fp16.h>

#define N_NODES_MAX 100000
#define NE_MAX 1600000
#define N_GRAPHS 256
#define HID 64
#define N_TASKS 10
#define EPG 32   // edges per 16-thread group chunk (dst-sorted)

// ---------------- scratch (no allocations allowed) ----------------
__device__ __align__(16) float d_agg[N_NODES_MAX * HID];
__device__ __align__(16) float d_hA[N_NODES_MAX * HID];
__device__ __align__(16) float d_hB[N_NODES_MAX * HID];
__device__ __align__(16) float d_pooled[N_GRAPHS * HID];
__device__ __align__(16) float d_cnt[N_GRAPHS];
__device__ __align__(16) float d_W12[16 * 128];   // [We1 | We1@We2]
__device__ __align__(16) float d_b12[128];        // [be1 | be1@We2+be2]
// CSR / sorted-edge scratch
__device__ int d_hist[N_NODES_MAX];
__device__ int d_cur[N_NODES_MAX];
__device__ int d_offs[N_NODES_MAX + 1];
__device__ int d_bsum[128];
__device__ int d_pos[NE_MAX];                     // pos[e] = sorted position of edge e
__device__ __align__(8) int2 d_sd[NE_MAX];        // packed (src, dst) in sorted order
// transformed edge features, dst-sorted order, bias included, fp16 (205 MB each)
__device__ __align__(16) __half d_ea1h[(long long)NE_MAX * HID];
__device__ __align__(16) __half d_ea2h[(long long)NE_MAX * HID];

// ---------------- prep ----------------
__global__ void prep_kernel(const float* __restrict__ We1, const float* __restrict__ be1,
                            const float* __restrict__ We2, const float* __restrict__ be2,
                            float* __restrict__ W12, float* __restrict__ b12) {
    int idx = blockIdx.x * blockDim.x + threadIdx.x;
    if (idx < 16 * 128) {
        int k = idx >> 7, j = idx & 127;
        if (j < 64) {
            W12[idx] = We1[k * HID + j];
        } else {
            int jj = j - 64;
            float acc = 0.f;
            #pragma unroll 8
            for (int m = 0; m < HID; m++) acc += We1[k * HID + m] * We2[m * HID + jj];
            W12[idx] = acc;
        }
    } else if (idx < 16 * 128 + 128) {
        int j = idx - 16 * 128;
        if (j < 64) {
            b12[j] = be1[j];
        } else {
            int jj = j - 64;
            float acc = be2[jj];
            #pragma unroll 8
            for (int m = 0; m < HID; m++) acc += be1[m] * We2[m * HID + jj];
            b12[j] = acc;
        }
    }
}

// ---------------- CSR build ----------------
__global__ void hist_kernel(const int* __restrict__ dst, int* __restrict__ hist, int nE) {
    int e = blockIdx.x * blockDim.x + threadIdx.x;
    if (e < nE) atomicAdd(&hist[__ldcs(dst + e)], 1);
}

__global__ void scan_block_kernel(const int* __restrict__ hist, int* __restrict__ offs,
                                  int* __restrict__ bsum, int nN) {
    __shared__ int s[1024];
    int i = blockIdx.x * 1024 + threadIdx.x;
    int v = (i < nN) ? hist[i] : 0;
    s[threadIdx.x] = v;
    __syncthreads();
    for (int off = 1; off < 1024; off <<= 1) {
        int add = (threadIdx.x >= off) ? s[threadIdx.x - off] : 0;
        __syncthreads();
        s[threadIdx.x] += add;
        __syncthreads();
    }
    if (i < nN) offs[i] = s[threadIdx.x] - v;
    if (threadIdx.x == 1023) bsum[blockIdx.x] = s[1023];
}
__global__ void scan_top_kernel(int* __restrict__ bsum, int nB) {
    __shared__ int s[128];
    int v = (threadIdx.x < nB) ? bsum[threadIdx.x] : 0;
    s[threadIdx.x] = v;
    __syncthreads();
    for (int off = 1; off < 128; off <<= 1) {
        int add = (threadIdx.x >= off) ? s[threadIdx.x - off] : 0;
        __syncthreads();
        s[threadIdx.x] += add;
        __syncthreads();
    }
    if (threadIdx.x < nB) bsum[threadIdx.x] = s[threadIdx.x] - v;
}
__global__ void scan_add_kernel(int* __restrict__ offs, const int* __restrict__ bsum,
                                int nN, int nE) {
    int i = blockIdx.x * 1024 + threadIdx.x;
    if (i < nN) offs[i] += bsum[blockIdx.x];
    if (i == 0) offs[nN] = nE;
}

// also records pos[e] = sorted slot of edge e (inverse permutation)
__global__ void scatter_kernel(const int* __restrict__ src, const int* __restrict__ dst,
                               const int* __restrict__ offs, int* __restrict__ cur,
                               int* __restrict__ pos, int2* __restrict__ sd, int nE) {
    int e = blockIdx.x * blockDim.x + threadIdx.x;
    if (e < nE) {
        int d = __ldcs(dst + e);
        int s = __ldcs(src + e);
        int p = atomicAdd(&cur[d], 1);
        int i = offs[d] + p;
        pos[e] = i;
        sd[i] = make_int2(s, d);
    }
}

// ---------------- transform (original order in, scattered full-line writes out) ----------------
__global__ void __launch_bounds__(256) transform_kernel(
    const float* __restrict__ ea,      // [E,16] original order (streamed)
    const int* __restrict__ pos,       // [E] sorted position per edge (streamed)
    const float* __restrict__ W12,     // [16,128]
    const float* __restrict__ b12,     // [128]
    __half* __restrict__ ea1h,         // [E,64] sorted
    __half* __restrict__ ea2h,         // [E,64] sorted
    int nE)
{
    const int lane = threadIdx.x & 31;
    const int t16 = lane & 15;
    long long warp = blockIdx.x * (blockDim.x >> 5) + (threadIdx.x >> 5);
    const long long stride = (long long)gridDim.x * (blockDim.x >> 5) * 4;

    float4 w[16];
    #pragma unroll
    for (int k = 0; k < 16; k++) w[k] = *(const float4*)(W12 + k * 128 + 4 * lane);
    const float4 bv = *(const float4*)(b12 + 4 * lane);

    for (long long i = warp * 4; i < nE; i += stride) {
        float ev[4];
        int ps[4];
        #pragma unroll
        for (int u = 0; u < 4; u++) {
            long long e = i + u; if (e >= nE) e = nE - 1;
            ev[u] = __ldcs(ea + e * 16 + t16);   // sequential, coalesced
            ps[u] = __ldcs(pos + e);             // sequential, broadcast across warp
        }

        #pragma unroll
        for (int u = 0; u < 4; u++) {
            if (i + u < nE) {
                float a0 = bv.x, a1 = bv.y, a2 = bv.z, a3 = bv.w;
                #pragma unroll
                for (int k = 0; k < 16; k++) {
                    float av = __shfl_sync(0xffffffffu, ev[u], k);
                    a0 += av * w[k].x;
                    a1 += av * w[k].y;
                    a2 += av * w[k].z;
                    a3 += av * w[k].w;
                }
                __half2 p0 = __floats2half2_rn(a0, a1);
                __half2 p1 = __floats2half2_rn(a2, a3);
                int2 pk;
                pk.x = *reinterpret_cast<int*>(&p0);
                pk.y = *reinterpret_cast<int*>(&p1);
                long long row = (long long)ps[u] * HID;
                if (lane < 16) __stcs(reinterpret_cast<int2*>(ea1h + row + 4 * lane), pk);
                else           __stcs(reinterpret_cast<int2*>(ea2h + row + 4 * (lane - 16)), pk);
            }
        }
    }
}

// ---------------- streaming edge phase: segmented sum of relu(x[src] + ea_row) ----------------
// 16 threads per chunk of EPG dst-sorted edges. (src,dst) pairs preloaded into registers
// and broadcast via half-warp shfl. Inner loop processes groups of 4 with an explicit
// load phase (8 loads in flight, no intervening branches) then an accumulate/flush phase.
__global__ void __launch_bounds__(256) edge_stream_kernel(
    const float* __restrict__ xin,
    const __half* __restrict__ eamh,  // [E,64] sorted fp16, bias included
    const int2* __restrict__ sd,      // packed (src,dst), sorted
    float* __restrict__ agg,
    int nE)
{
    const int tid = threadIdx.x;
    const int t = tid & 15;
    const int g = tid >> 4;
    const unsigned shfl_base = (tid & 31) & 16;
    const unsigned mask = 0xFFFFu << shfl_base;

    long long base = (long long)(blockIdx.x * 16 + g) * EPG;
    if (base >= nE) return;

    long long i0 = base + 2 * t;     if (i0 > (long long)nE - 1) i0 = nE - 1;
    long long i1 = i0 + 1;           if (i1 > (long long)nE - 1) i1 = nE - 1;
    int2 my0 = __ldcs(&sd[i0]);
    int2 my1 = __ldcs(&sd[i1]);

    int curd = __shfl_sync(mask, my0.y, shfl_base);
    float4 acc = make_float4(0.f, 0.f, 0.f, 0.f);

    if (base + EPG <= nE) {
        #pragma unroll
        for (int ii = 0; ii < EPG; ii += 4) {
            // ---- load phase: all addresses resolved, 8 loads issued back-to-back ----
            int sx[4], dy[4];
            int2 er[4];
            float4 xv[4];
            #pragma unroll
            for (int u = 0; u < 4; u++) {
                int i = ii + u;
                sx[u] = __shfl_sync(mask, (i & 1) ? my1.x : my0.x, shfl_base + (i >> 1));
                dy[u] = __shfl_sync(mask, (i & 1) ? my1.y : my0.y, shfl_base + (i >> 1));
            }
            #pragma unroll
            for (int u = 0; u < 4; u++) {
                er[u] = __ldcs(reinterpret_cast<const int2*>(eamh + (base + ii + u) * HID + 4 * t));
                xv[u] = *(const float4*)(xin + (long long)sx[u] * HID + 4 * t);
            }
            // ---- accumulate / flush phase ----
            #pragma unroll
            for (int u = 0; u < 4; u++) {
                if (dy[u] != curd) {
                    atomicAdd((float4*)(agg + (long long)curd * HID + 4 * t), acc);
                    acc = make_float4(0.f, 0.f, 0.f, 0.f);
                    curd = dy[u];
                }
                __half2 h0 = *reinterpret_cast<__half2*>(&er[u].x);
                __half2 h1 = *reinterpret_cast<__half2*>(&er[u].y);
                float2 e0 = __half22float2(h0);
                float2 e1 = __half22float2(h1);
                acc.x += fmaxf(xv[u].x + e0.x, 0.f);
                acc.y += fmaxf(xv[u].y + e0.y, 0.f);
                acc.z += fmaxf(xv[u].z + e1.x, 0.f);
                acc.w += fmaxf(xv[u].w + e1.y, 0.f);
            }
        }
    } else {
        int cnt = (int)(nE - base);
        for (int i = 0; i < cnt; i++) {
            int sx = __shfl_sync(mask, (i & 1) ? my1.x : my0.x, shfl_base + (i >> 1));
            int dy = __shfl_sync(mask, (i & 1) ? my1.y : my0.y, shfl_base + (i >> 1));
            if (dy != curd) {
                atomicAdd((float4*)(agg + (long long)curd * HID + 4 * t), acc);
                acc = make_float4(0.f, 0.f, 0.f, 0.f);
                curd = dy;
            }
            int2 raw = __ldcs(reinterpret_cast<const int2*>(eamh + (base + i) * HID + 4 * t));
            __half2 h0 = *reinterpret_cast<__half2*>(&raw.x);
            __half2 h1 = *reinterpret_cast<__half2*>(&raw.y);
            float2 e0 = __half22float2(h0);
            float2 e1 = __half22float2(h1);
            float4 xv = *(const float4*)(xin + (long long)sx * HID + 4 * t);
            acc.x += fmaxf(xv.x + e0.x, 0.f);
            acc.y += fmaxf(xv.y + e0.y, 0.f);
            acc.z += fmaxf(xv.z + e1.x, 0.f);
            acc.w += fmaxf(xv.w + e1.y, 0.f);
        }
    }
    atomicAdd((float4*)(agg + (long long)curd * HID + 4 * t), acc);
}

// ---------------- node phase (persistent) ----------------
template <bool RELU>
__global__ void __launch_bounds__(128) node_kernel(
    const float* __restrict__ xin,
    const float* __restrict__ agg,
    const float* __restrict__ W,     // [64,64]
    const float* __restrict__ b,
    const float* __restrict__ epsp,
    float* __restrict__ out,
    int nN)
{
    __shared__ float srow[8][HID];
    const int j = threadIdx.x & 63;
    const int slot = threadIdx.x >> 6;
    const float scale = 1.f + epsp[0];

    float wc[HID];
    #pragma unroll
    for (int k = 0; k < HID; k++) wc[k] = W[k * HID + j];
    const float bj = b[j];

    for (int base = blockIdx.x * 8; base < nN; base += gridDim.x * 8) {
        #pragma unroll
        for (int r = 0; r < 4; r++) {
            int n = base + slot * 4 + r;
            if (n < nN)
                srow[slot * 4 + r][j] = scale * xin[(long long)n * HID + j] + agg[(long long)n * HID + j];
        }
        __syncthreads();

        float a0 = bj, a1 = bj, a2 = bj, a3 = bj;
        #pragma unroll
        for (int k = 0; k < HID; k += 4) {
            float4 r0 = *(const float4*)&srow[slot * 4 + 0][k];
            float4 r1 = *(const float4*)&srow[slot * 4 + 1][k];
            float4 r2 = *(const float4*)&srow[slot * 4 + 2][k];
            float4 r3 = *(const float4*)&srow[slot * 4 + 3][k];
            a0 += r0.x * wc[k] + r0.y * wc[k + 1] + r0.z * wc[k + 2] + r0.w * wc[k + 3];
            a1 += r1.x * wc[k] + r1.y * wc[k + 1] + r1.z * wc[k + 2] + r1.w * wc[k + 3];
            a2 += r2.x * wc[k] + r2.y * wc[k + 1] + r2.z * wc[k + 2] + r2.w * wc[k + 3];
            a3 += r3.x * wc[k] + r3.y * wc[k + 1] + r3.z * wc[k + 2] + r3.w * wc[k + 3];
        }

        int n0 = base + slot * 4;
        if (n0 + 0 < nN) out[(long long)(n0 + 0) * HID + j] = RELU ? fmaxf(a0, 0.f) : a0;
        if (n0 + 1 < nN) out[(long long)(n0 + 1) * HID + j] = RELU ? fmaxf(a1, 0.f) : a1;
        if (n0 + 2 < nN) out[(long long)(n0 + 2) * HID + j] = RELU ? fmaxf(a2, 0.f) : a2;
        if (n0 + 3 < nN) out[(long long)(n0 + 3) * HID + j] = RELU ? fmaxf(a3, 0.f) : a3;
        __syncthreads();
    }
}

// ---------------- pooling: scatter-mean over sorted batch ----------------
__global__ void pool_kernel(const float* __restrict__ h,
                            const int* __restrict__ batch,
                            float* __restrict__ pooled,
                            float* __restrict__ cnt,
                            int nN)
{
    const int j = threadIdx.x & 63;
    const int p = threadIdx.x >> 6;
    const int CHUNK = 512;
    int base = blockIdx.x * CHUNK;
    int lim = base + CHUNK;
    if (lim > nN) lim = nN;

    float acc = 0.f;
    float c = 0.f;
    int curg = -1;
    for (int n = base + p; n < lim; n += 4) {
        int g = batch[n];
        if (g != curg) {
            if (curg >= 0) {
                atomicAdd(&pooled[curg * HID + j], acc);
                if (j == 0) atomicAdd(&cnt[curg], c);
            }
            acc = 0.f; c = 0.f; curg = g;
        }
        acc += h[(long long)n * HID + j];
        c += 1.f;
    }
    if (curg >= 0) {
        atomicAdd(&pooled[curg * HID + j], acc);
        if (j == 0) atomicAdd(&cnt[curg], c);
    }
}

// ---------------- head ----------------
__global__ void head_kernel(const float* __restrict__ pooled,
                            const float* __restrict__ cnt,
                            const float* __restrict__ Wm1, const float* __restrict__ bm1,
                            const float* __restrict__ Wm2, const float* __restrict__ bm2,
                            float* __restrict__ out)
{
    int gq = blockIdx.x * blockDim.x + threadIdx.x;
    if (gq >= N_GRAPHS) return;
    float inv = 1.f / fmaxf(cnt[gq], 1.f);
    float row[HID];
    #pragma unroll
    for (int k = 0; k < HID; k++) row[k] = pooled[gq * HID + k] * inv;
    float o[N_TASKS];
    #pragma unroll
    for (int ts = 0; ts < N_TASKS; ts++) o[ts] = bm2[ts];
    for (int jj = 0; jj < HID; jj++) {
        float hv = bm1[jj];
        #pragma unroll 16
        for (int k = 0; k < HID; k++) hv += row[k] * Wm1[k * HID + jj];
        hv = fmaxf(hv, 0.f);
        #pragma unroll
        for (int ts = 0; ts < N_TASKS; ts++) o[ts] += hv * Wm2[jj * N_TASKS + ts];
    }
    #pragma unroll
    for (int ts = 0; ts < N_TASKS; ts++) out[gq * N_TASKS + ts] = o[ts];
}

// ---------------- launch ----------------
extern "C" void kernel_launch(void* const* d_in, const int* in_sizes, int n_in,
                              void* d_out, int out_size) {
    const float* x         = (const float*)d_in[0];
    const int*   eidx      = (const int*)d_in[1];
    const float* edge_attr = (const float*)d_in[2];
    const int*   batch     = (const int*)d_in[3];
    const float* We1 = (const float*)d_in[4];
    const float* be1 = (const float*)d_in[5];
    const float* We2 = (const float*)d_in[6];
    const float* be2 = (const float*)d_in[7];
    const float* W1  = (const float*)d_in[8];
    const float* b1  = (const float*)d_in[9];
    const float* e1  = (const float*)d_in[10];
    const float* W2  = (const float*)d_in[11];
    const float* b2  = (const float*)d_in[12];
    const float* e2  = (const float*)d_in[13];
    const float* W3  = (const float*)d_in[14];
    const float* b3  = (const float*)d_in[15];
    const float* e3  = (const float*)d_in[16];
    const float* Wm1 = (const float*)d_in[17];
    const float* bm1 = (const float*)d_in[18];
    const float* Wm2 = (const float*)d_in[19];
    const float* bm2 = (const float*)d_in[20];
    float* out = (float*)d_out;

    int nN = in_sizes[0] / HID;       // 100000
    int nE = in_sizes[2] / 16;        // 1600000
    const int* src = eidx;
    const int* dst = eidx + nE;

    float *agg, *hA, *hB, *pooled, *cnt, *W12, *b12;
    __half *ea1h, *ea2h;
    int *hist, *cur, *offs, *bsum, *pos;
    int2 *sd;
    cudaGetSymbolAddress((void**)&agg,    d_agg);
    cudaGetSymbolAddress((void**)&hA,     d_hA);
    cudaGetSymbolAddress((void**)&hB,     d_hB);
    cudaGetSymbolAddress((void**)&pooled, d_pooled);
    cudaGetSymbolAddress((void**)&cnt,    d_cnt);
    cudaGetSymbolAddress((void**)&W12,    d_W12);
    cudaGetSymbolAddress((void**)&b12,    d_b12);
    cudaGetSymbolAddress((void**)&hist,   d_hist);
    cudaGetSymbolAddress((void**)&cur,    d_cur);
    cudaGetSymbolAddress((void**)&offs,   d_offs);
    cudaGetSymbolAddress((void**)&bsum,   d_bsum);
    cudaGetSymbolAddress((void**)&pos,    d_pos);
    cudaGetSymbolAddress((void**)&sd,     d_sd);
    cudaGetSymbolAddress((void**)&ea1h,   d_ea1h);
    cudaGetSymbolAddress((void**)&ea2h,   d_ea2h);

    const int ZB = 256;
    const int eBlocks = (nE + ZB - 1) / ZB;
    const size_t aggBytes = (size_t)nN * HID * sizeof(float);
    const int streamBlocks = (nE + 16 * EPG - 1) / (16 * EPG);
    const int scanBlocks = (nN + 1023) / 1024;
    const int NODE_GRID = 592;

    prep_kernel<<<(16 * 128 + 128 + 127) / 128, 128>>>(We1, be1, We2, be2, W12, b12);

    // ---- sort edges by dst (CSR), hierarchical scan ----
    cudaMemsetAsync(hist, 0, (size_t)nN * sizeof(int));
    cudaMemsetAsync(cur,  0, (size_t)nN * sizeof(int));
    hist_kernel<<<eBlocks, ZB>>>(dst, hist, nE);
    scan_block_kernel<<<scanBlocks, 1024>>>(hist, offs, bsum, nN);
    scan_top_kernel<<<1, 128>>>(bsum, scanBlocks);
    scan_add_kernel<<<scanBlocks, 1024>>>(offs, bsum, nN, nE);
    scatter_kernel<<<eBlocks, ZB>>>(src, dst, offs, cur, pos, sd, nE);

    // ---- transform: stream ea in original order, scatter full-line fp16 outputs ----
    transform_kernel<<<1184, 256>>>(edge_attr, pos, W12, b12, ea1h, ea2h, nE);

    // ---- conv1 ----
    cudaMemsetAsync(agg, 0, aggBytes);
    edge_stream_kernel<<<streamBlocks, 256>>>(x, ea1h, sd, agg, nE);
    node_kernel<true><<<NODE_GRID, 128>>>(x, agg, W1, b1, e1, hA, nN);

    // ---- conv2 ----
    cudaMemsetAsync(agg, 0, aggBytes);
    edge_stream_kernel<<<streamBlocks, 256>>>(hA, ea2h, sd, agg, nE);
    node_kernel<true><<<NODE_GRID, 128>>>(hA, agg, W2, b2, e2, hB, nN);

    // ---- conv3 ----
    cudaMemsetAsync(agg, 0, aggBytes);
    edge_stream_kernel<<<streamBlocks, 256>>>(hB, ea2h, sd, agg, nE);
    node_kernel<false><<<NODE_GRID, 128>>>(hB, agg, W3, b3, e3, hA, nN);

    // ---- pooling + head ----
    cudaMemsetAsync(pooled, 0, N_GRAPHS * HID * sizeof(float));
    cudaMemsetAsync(cnt, 0, N_GRAPHS * sizeof(float));
    pool_kernel<<<(nN + 511) / 512, 256>>>(hA, batch, pooled, cnt, nN);
    head_kernel<<<1, 256>>>(pooled, cnt, Wm1, bm1, Wm2, bm2, out);
}